// round 7
// baseline (speedup 1.0000x reference)
#include <cuda_runtime.h>
#include <cuda_bf16.h>
#include <cstdint>

// ---------------- problem constants ----------------
#define NQ      256
#define DDIM    256
#define NDB     500000
#define TILE    32
#define NTILES  (NDB / TILE)          // 15625, exact
#define GRID    152
#define MARGIN  5e-3f
#define EPSN    1e-8f
#define QMAX    126.5f
#define CAP     (8u * 1024u * 1024u)  // record buffer entries

// ---------------- smem layout ----------------------
// [0, 128)        dscale for 32 db rows
// [128, 1152)     qscale for 256 query rows
// [2048, 67584)   Q int8 image: 256 rows x 256B, swizzled
// [67584, 75776)  DB tile int8: 32 rows x 256B, swizzled
#define QSC_OFF    128
#define QBASE      2048
#define QBYTES     (NQ * 256)
#define DBBASE     (QBASE + QBYTES)
#define DBBYTES    (TILE * 256)
#define SMEM_TOTAL (DBBASE + DBBYTES) // 75776

// swizzled byte offset: u = 16B-unit index within a 256B row (0..15)
#define SWZ8(row, u) (((uint32_t)(row)) * 256u + ((uint32_t)((u) ^ ((row) & 7)) << 4))

__device__ __align__(16) unsigned char g_qn[QBYTES];  // prebuilt swizzled int8 queries
__device__ float              g_qscale[NQ];           // maxabs(q_hat)/QMAX
__device__ float              g_qnorm[NQ];
__device__ unsigned int       g_best[NQ];             // sortable-u32 int8-sim best
__device__ unsigned long long g_final[NQ];            // (sortable exact sim | ~idx)
__device__ unsigned int       g_cnt;
__device__ unsigned long long g_rec[CAP];

// ---------------- helpers ----------------------
__device__ __forceinline__ uint32_t smem_u32(const void* p) {
    uint32_t a;
    asm("{ .reg .u64 t; cvta.to.shared.u64 t, %1; cvt.u32.u64 %0, t; }" : "=r"(a) : "l"(p));
    return a;
}
__device__ __forceinline__ uint32_t f_sort(float x) {
    uint32_t s = __float_as_uint(x);
    return (s & 0x80000000u) ? ~s : (s | 0x80000000u);
}
__device__ __forceinline__ float f_unsort(uint32_t s) {
    return __uint_as_float((s & 0x80000000u) ? (s & 0x7FFFFFFFu) : ~s);
}
__device__ __forceinline__ uint32_t pack_s8x4(float a, float b, float c, float d) {
    int ia = __float2int_rn(a), ib = __float2int_rn(b);
    int ic = __float2int_rn(c), id = __float2int_rn(d);
    return (uint32_t)(ia & 255) | ((uint32_t)(ib & 255) << 8)
         | ((uint32_t)(ic & 255) << 16) | ((uint32_t)(id & 255) << 24);
}
#define LDSM4(r, addr)                                                        \
    asm volatile("ldmatrix.sync.aligned.m8n8.x4.shared.b16 {%0,%1,%2,%3}, [%4];" \
        : "=r"((r)[0]), "=r"((r)[1]), "=r"((r)[2]), "=r"((r)[3]) : "r"(addr))

__device__ __forceinline__ void imma16832(int* c, const uint32_t* a, const uint32_t* b) {
    asm volatile("mma.sync.aligned.m16n8k32.row.col.s32.s8.s8.s32 "
        "{%0,%1,%2,%3}, {%4,%5,%6,%7}, {%8,%9}, {%0,%1,%2,%3};"
        : "+r"(c[0]), "+r"(c[1]), "+r"(c[2]), "+r"(c[3])
        : "r"(a[0]), "r"(a[1]), "r"(a[2]), "r"(a[3]), "r"(b[0]), "r"(b[1]));
}

// ============ kernel 1: normalize + int8-quantize queries; init globals ============
__global__ void prep_kernel(const float* __restrict__ q) {
    int gtid = blockIdx.x * blockDim.x + threadIdx.x;
    if (gtid < NQ) { g_best[gtid] = 0u; g_final[gtid] = 0ull; }
    if (gtid == 0) g_cnt = 0u;
    int qi = gtid >> 5, lane = gtid & 31;
    if (qi >= NQ) return;
    const float4* row = reinterpret_cast<const float4*>(q + (size_t)qi * DDIM);
    float4 a = row[lane * 2], b = row[lane * 2 + 1];
    float ssq = a.x * a.x + a.y * a.y + a.z * a.z + a.w * a.w
              + b.x * b.x + b.y * b.y + b.z * b.z + b.w * b.w;
    float mx = fmaxf(fmaxf(fmaxf(fabsf(a.x), fabsf(a.y)), fmaxf(fabsf(a.z), fabsf(a.w))),
                     fmaxf(fmaxf(fabsf(b.x), fabsf(b.y)), fmaxf(fabsf(b.z), fabsf(b.w))));
#pragma unroll
    for (int o = 16; o; o >>= 1) {
        ssq += __shfl_xor_sync(0xFFFFFFFFu, ssq, o);
        mx = fmaxf(mx, __shfl_xor_sync(0xFFFFFFFFu, mx, o));
    }
    float nrm = sqrtf(ssq);
    float rn = 1.f / fmaxf(nrm, EPSN);
    float mhat = mx * rn;                       // maxabs of normalized row
    float s = QMAX / fmaxf(mhat, 1e-30f);       // quant scale (no saturation possible)
    if (lane == 0) { g_qnorm[qi] = nrm; g_qscale[qi] = mhat / QMAX; }
    float qs = rn * s;
    uint2 pk;
    pk.x = pack_s8x4(a.x * qs, a.y * qs, a.z * qs, a.w * qs);
    pk.y = pack_s8x4(b.x * qs, b.y * qs, b.z * qs, b.w * qs);
    *reinterpret_cast<uint2*>(g_qn + SWZ8(qi, lane >> 1) + (lane & 1) * 8) = pk;
}

// ============ kernel 2: persistent int8 IMMA GEMM + margin-filtered argmax ============
__global__ void __launch_bounds__(256) main_kernel(const float* __restrict__ db) {
    extern __shared__ char smem[];
    float* dsc_s = reinterpret_cast<float*>(smem);
    float* qsc_s = reinterpret_cast<float*>(smem + QSC_OFF);
    const int tid = threadIdx.x;
    const int lane = tid & 31, warp = tid >> 5;
    const uint32_t sb = smem_u32(smem);
    const uint32_t qsm = sb + QBASE, dsm = sb + DBBASE;

    // copy prebuilt query image (64 KB) + qscales into SMEM
    {
        const uint4* src = reinterpret_cast<const uint4*>(g_qn);
        uint4* dst = reinterpret_cast<uint4*>(smem + QBASE);
#pragma unroll
        for (int i = 0; i < 16; i++) dst[tid + i * 256] = src[tid + i * 256];
        if (tid < NQ) qsc_s[tid] = g_qscale[tid];
    }

    // db tile load mapping: thread -> (row = tid/8, 32 cols starting at (tid&7)*32)
    const int lrow = tid >> 3, le8 = tid & 7;
    float4 v[8];
    int tile = blockIdx.x;
    {
        const float4* g = reinterpret_cast<const float4*>(
            db + (size_t)(tile * TILE + lrow) * DDIM) + le8 * 8;
#pragma unroll
        for (int i = 0; i < 8; i++) v[i] = g[i];
    }
    __syncthreads();

    // MMA lane-invariant addressing (identical fragment bytes to verified bf16 path)
    const int mbase = warp * 32;
    const int rA0 = mbase + (lane & 15);
    const int rA1 = rA0 + 16;
    const int rB0 = (lane & 7) + ((lane >> 4) & 1) * 8;
    const int rB1 = rB0 + 16;
    const int gq = lane >> 2, tc = lane & 3;

    // per-thread query scales (rows fixed across the whole loop)
    float qs4[4];
#pragma unroll
    for (int mb = 0; mb < 2; mb++)
#pragma unroll
        for (int hf = 0; hf < 2; hf++)
            qs4[mb * 2 + hf] = qsc_s[mbase + mb * 16 + hf * 8 + gq];

    float best[4] = {-2.f, -2.f, -2.f, -2.f};

    for (; tile < NTILES; tile += GRID) {
        // ---- quantize staged fp32 -> int8 swizzled smem; per-row scale ----
        float ssq = 0.f, mx = 0.f;
#pragma unroll
        for (int i = 0; i < 8; i++) {
            ssq += v[i].x * v[i].x + v[i].y * v[i].y + v[i].z * v[i].z + v[i].w * v[i].w;
            mx = fmaxf(mx, fmaxf(fmaxf(fabsf(v[i].x), fabsf(v[i].y)),
                                 fmaxf(fabsf(v[i].z), fabsf(v[i].w))));
        }
#pragma unroll
        for (int o = 1; o < 8; o <<= 1) {
            ssq += __shfl_xor_sync(0xFFFFFFFFu, ssq, o);
            mx = fmaxf(mx, __shfl_xor_sync(0xFFFFFFFFu, mx, o));
        }
        float s = QMAX / fmaxf(mx, 1e-30f);
        if (le8 == 0)
            dsc_s[lrow] = (mx / QMAX) / fmaxf(sqrtf(ssq), EPSN);
        {
            uint4 pk;
            pk.x = pack_s8x4(v[0].x * s, v[0].y * s, v[0].z * s, v[0].w * s);
            pk.y = pack_s8x4(v[1].x * s, v[1].y * s, v[1].z * s, v[1].w * s);
            pk.z = pack_s8x4(v[2].x * s, v[2].y * s, v[2].z * s, v[2].w * s);
            pk.w = pack_s8x4(v[3].x * s, v[3].y * s, v[3].z * s, v[3].w * s);
            *reinterpret_cast<uint4*>(smem + DBBASE + SWZ8(lrow, le8 * 2)) = pk;
            pk.x = pack_s8x4(v[4].x * s, v[4].y * s, v[4].z * s, v[4].w * s);
            pk.y = pack_s8x4(v[5].x * s, v[5].y * s, v[5].z * s, v[5].w * s);
            pk.z = pack_s8x4(v[6].x * s, v[6].y * s, v[6].z * s, v[6].w * s);
            pk.w = pack_s8x4(v[7].x * s, v[7].y * s, v[7].z * s, v[7].w * s);
            *reinterpret_cast<uint4*>(smem + DBBASE + SWZ8(lrow, le8 * 2 + 1)) = pk;
        }
        __syncthreads();

        // ---- prefetch next tile into registers (drains during MMA) ----
        int nt = tile + GRID;
        if (nt < NTILES) {
            const float4* g = reinterpret_cast<const float4*>(
                db + (size_t)(nt * TILE + lrow) * DDIM) + le8 * 8;
#pragma unroll
            for (int i = 0; i < 8; i++) v[i] = g[i];
        }

        // ---- IMMA: warp computes [mbase..mbase+32) x [0..32) over K=256 int8 ----
        int acc[2][4][4];
#pragma unroll
        for (int mb = 0; mb < 2; mb++)
#pragma unroll
            for (int nb = 0; nb < 4; nb++)
#pragma unroll
                for (int c = 0; c < 4; c++) acc[mb][nb][c] = 0;

#pragma unroll
        for (int ks = 0; ks < 8; ks++) {   // 8 x k32 = K 256
            const int ua = ks * 2 + (lane >> 4);
            uint32_t a[2][4];
            LDSM4(a[0], qsm + SWZ8(rA0, ua));
            LDSM4(a[1], qsm + SWZ8(rA1, ua));
            const int ub = ks * 2 + ((lane >> 3) & 1);
            uint32_t b[4][2];
            {
                uint32_t r[4];
                LDSM4(r, dsm + SWZ8(rB0, ub));
                b[0][0] = r[0]; b[0][1] = r[1]; b[1][0] = r[2]; b[1][1] = r[3];
                LDSM4(r, dsm + SWZ8(rB1, ub));
                b[2][0] = r[0]; b[2][1] = r[1]; b[3][0] = r[2]; b[3][1] = r[3];
            }
#pragma unroll
            for (int mb = 0; mb < 2; mb++)
#pragma unroll
                for (int nb = 0; nb < 4; nb++)
                    imma16832(acc[mb][nb], a[mb], b[nb]);
        }

        // ---- epilogue: scale to cosine sim, margin-filtered running argmax ----
        float2 ds2[4];
#pragma unroll
        for (int nb = 0; nb < 4; nb++)
            ds2[nb] = *reinterpret_cast<const float2*>(&dsc_s[nb * 8 + tc * 2]);
#pragma unroll
        for (int mb = 0; mb < 2; mb++)
#pragma unroll
            for (int hf = 0; hf < 2; hf++) {
                const int ridx = mb * 2 + hf;
                const unsigned qrow = (unsigned)(mbase + mb * 16 + hf * 8 + gq);
                const float qs = qs4[ridx];
#pragma unroll
                for (int nb = 0; nb < 4; nb++)
#pragma unroll
                    for (int j = 0; j < 2; j++) {
                        float val = (float)acc[mb][nb][hf * 2 + j]
                                  * (qs * (j ? ds2[nb].y : ds2[nb].x));
                        if (val >= best[ridx] - MARGIN) {
                            unsigned idx = (unsigned)(tile * TILE + nb * 8 + tc * 2 + j);
                            unsigned pos = atomicAdd(&g_cnt, 1u);
                            if (pos < CAP)
                                g_rec[pos] = ((unsigned long long)f_sort(val) << 32)
                                           | ((unsigned long long)qrow << 20) | idx;
                            if (val > best[ridx]) best[ridx] = val;
                        }
                    }
            }
        __syncthreads();
    }

    // publish per-thread int8-sim bests (threshold source for rescue filter)
#pragma unroll
    for (int k = 0; k < 4; k++) {
        unsigned qrow = (unsigned)(mbase + (k >> 1) * 16 + (k & 1) * 8 + gq);
        atomicMax(&g_best[qrow], f_sort(best[k]));
    }
}

// ============ kernel 3: filter records, recompute exact fp32 sims for survivors ============
__global__ void rescue_kernel(const float* __restrict__ q, const float* __restrict__ db) {
    unsigned n = g_cnt;
    if (n > CAP) n = CAP;
    for (unsigned i = blockIdx.x * blockDim.x + threadIdx.x; i < n;
         i += gridDim.x * blockDim.x) {
        unsigned long long rec = g_rec[i];
        float simq = f_unsort((uint32_t)(rec >> 32));
        unsigned qi = (unsigned)(rec >> 20) & 0xFFu;
        unsigned idx = (unsigned)(rec & 0xFFFFFu);
        if (simq < f_unsort(g_best[qi]) - MARGIN) continue;
        const float4* qr = reinterpret_cast<const float4*>(q) + qi * (DDIM / 4);
        const float4* dr = reinterpret_cast<const float4*>(db) + (size_t)idx * (DDIM / 4);
        float dot = 0.f, dsq = 0.f;
#pragma unroll 8
        for (int k = 0; k < DDIM / 4; k++) {
            float4 a = qr[k], b = dr[k];
            dot += a.x * b.x + a.y * b.y + a.z * b.z + a.w * b.w;
            dsq += b.x * b.x + b.y * b.y + b.z * b.z + b.w * b.w;
        }
        float sim = dot / (fmaxf(g_qnorm[qi], EPSN) * fmaxf(sqrtf(dsq), EPSN));
        unsigned long long key = ((unsigned long long)f_sort(sim) << 32)
                               | (unsigned long long)(~idx);
        atomicMax(&g_final[qi], key);
    }
}

// ============ kernel 4: unpack, gather labels, write output ============
__global__ void finalize_kernel(const void* __restrict__ labels, float* __restrict__ out,
                                int out_size) {
    __shared__ int is32;
    if (threadIdx.x == 0) {
        const int* li = (const int*)labels;
        int nz = 0;
#pragma unroll
        for (int i = 0; i < 16; i++) nz |= li[2 * i + 1];
        is32 = nz;  // nonzero odd words -> int32 layout
    }
    __syncthreads();
    int qi = threadIdx.x;
    if (qi < NQ) {
        unsigned long long key = g_final[qi];
        float sim = f_unsort((uint32_t)(key >> 32));
        unsigned idx = ~((unsigned)(key & 0xFFFFFFFFull));
        long long lab;
        if (is32) lab = (long long)((const int*)labels)[idx];
        else      lab = ((const long long*)labels)[idx];
        out[qi] = sim;
        if (out_size >= 2 * NQ) out[NQ + qi] = (float)lab;
    }
}

// ============ entry point ============
extern "C" void kernel_launch(void* const* d_in, const int* in_sizes, int n_in,
                              void* d_out, int out_size) {
    (void)in_sizes; (void)n_in;
    const float* q  = (const float*)d_in[0];
    const float* db = (const float*)d_in[1];
    const void*  lb = d_in[2];
    float* out = (float*)d_out;

    cudaFuncSetAttribute(main_kernel, cudaFuncAttributeMaxDynamicSharedMemorySize, SMEM_TOTAL);

    prep_kernel<<<NQ * 32 / 256, 256>>>(q);
    main_kernel<<<GRID, 256, SMEM_TOTAL>>>(db);
    rescue_kernel<<<GRID, 256>>>(q, db);
    finalize_kernel<<<1, 256>>>(lb, out, out_size);
}

// round 8
// speedup vs baseline: 1.0050x; 1.0050x over previous
#include <cuda_runtime.h>
#include <cuda_bf16.h>
#include <cstdint>

// ---------------- problem constants ----------------
#define NQ      256
#define DDIM    256
#define NDB     500000
#define TILE    32
#define NTILES  (NDB / TILE)          // 15625, exact
#define GRID    152
#define MARGIN  5e-3f
#define EPSN    1e-8f
#define QMAX    126.5f
#define CAP     (8u * 1024u * 1024u)  // record buffer entries

// ---------------- smem layout ----------------------
// [0, 128)        dscale for 32 db rows
// [128, 1152)     qscale for 256 query rows
// [2048, 67584)   Q int8 image: 256 rows x 256B, swizzled
// [67584, 75776)  DB tile int8: 32 rows x 256B, swizzled
#define QSC_OFF    128
#define QBASE      2048
#define QBYTES     (NQ * 256)
#define DBBASE     (QBASE + QBYTES)
#define DBBYTES    (TILE * 256)
#define SMEM_TOTAL (DBBASE + DBBYTES) // 75776

// swizzled byte offset: u = 16B-unit index within a 256B row (0..15)
#define SWZ8(row, u) (((uint32_t)(row)) * 256u + ((uint32_t)((u) ^ ((row) & 7)) << 4))

__device__ __align__(16) unsigned char g_qn[QBYTES];  // prebuilt swizzled int8 queries
__device__ float              g_qscale[NQ];           // maxabs(q_hat)/QMAX
__device__ float              g_qnorm[NQ];
__device__ unsigned int       g_best[NQ];             // sortable-u32 int8-sim best
__device__ unsigned long long g_final[NQ];            // (sortable exact sim | ~idx)
__device__ unsigned int       g_cnt;
__device__ unsigned long long g_rec[CAP];

// ---------------- helpers ----------------------
__device__ __forceinline__ uint32_t smem_u32(const void* p) {
    uint32_t a;
    asm("{ .reg .u64 t; cvta.to.shared.u64 t, %1; cvt.u32.u64 %0, t; }" : "=r"(a) : "l"(p));
    return a;
}
__device__ __forceinline__ uint32_t f_sort(float x) {
    uint32_t s = __float_as_uint(x);
    return (s & 0x80000000u) ? ~s : (s | 0x80000000u);
}
__device__ __forceinline__ float f_unsort(uint32_t s) {
    return __uint_as_float((s & 0x80000000u) ? (s & 0x7FFFFFFFu) : ~s);
}
__device__ __forceinline__ uint32_t pack_s8x4(float a, float b, float c, float d) {
    int ia = __float2int_rn(a), ib = __float2int_rn(b);
    int ic = __float2int_rn(c), id = __float2int_rn(d);
    return (uint32_t)(ia & 255) | ((uint32_t)(ib & 255) << 8)
         | ((uint32_t)(ic & 255) << 16) | ((uint32_t)(id & 255) << 24);
}
#define LDSM4(r, addr)                                                        \
    asm volatile("ldmatrix.sync.aligned.m8n8.x4.shared.b16 {%0,%1,%2,%3}, [%4];" \
        : "=r"((r)[0]), "=r"((r)[1]), "=r"((r)[2]), "=r"((r)[3]) : "r"(addr))

__device__ __forceinline__ void imma16832(int* c, const uint32_t* a, const uint32_t* b) {
    asm volatile("mma.sync.aligned.m16n8k32.row.col.s32.s8.s8.s32 "
        "{%0,%1,%2,%3}, {%4,%5,%6,%7}, {%8,%9}, {%0,%1,%2,%3};"
        : "+r"(c[0]), "+r"(c[1]), "+r"(c[2]), "+r"(c[3])
        : "r"(a[0]), "r"(a[1]), "r"(a[2]), "r"(a[3]), "r"(b[0]), "r"(b[1]));
}

// ============ kernel 1: normalize + int8-quantize queries; init globals ============
__global__ void prep_kernel(const float* __restrict__ q) {
    int gtid = blockIdx.x * blockDim.x + threadIdx.x;
    if (gtid < NQ) { g_best[gtid] = 0u; g_final[gtid] = 0ull; }
    if (gtid == 0) g_cnt = 0u;
    int qi = gtid >> 5, lane = gtid & 31;
    if (qi >= NQ) return;
    const float4* row = reinterpret_cast<const float4*>(q + (size_t)qi * DDIM);
    float4 a = row[lane * 2], b = row[lane * 2 + 1];
    float ssq = a.x * a.x + a.y * a.y + a.z * a.z + a.w * a.w
              + b.x * b.x + b.y * b.y + b.z * b.z + b.w * b.w;
    float mx = fmaxf(fmaxf(fmaxf(fabsf(a.x), fabsf(a.y)), fmaxf(fabsf(a.z), fabsf(a.w))),
                     fmaxf(fmaxf(fabsf(b.x), fabsf(b.y)), fmaxf(fabsf(b.z), fabsf(b.w))));
#pragma unroll
    for (int o = 16; o; o >>= 1) {
        ssq += __shfl_xor_sync(0xFFFFFFFFu, ssq, o);
        mx = fmaxf(mx, __shfl_xor_sync(0xFFFFFFFFu, mx, o));
    }
    float nrm = sqrtf(ssq);
    float rn = 1.f / fmaxf(nrm, EPSN);
    float mhat = mx * rn;                       // maxabs of normalized row
    float s = QMAX / fmaxf(mhat, 1e-30f);       // quant scale (no saturation possible)
    if (lane == 0) { g_qnorm[qi] = nrm; g_qscale[qi] = mhat / QMAX; }
    float qs = rn * s;
    uint2 pk;
    pk.x = pack_s8x4(a.x * qs, a.y * qs, a.z * qs, a.w * qs);
    pk.y = pack_s8x4(b.x * qs, b.y * qs, b.z * qs, b.w * qs);
    *reinterpret_cast<uint2*>(g_qn + SWZ8(qi, lane >> 1) + (lane & 1) * 8) = pk;
}

// ============ kernel 2: persistent int8 IMMA GEMM + margin-filtered argmax ============
__global__ void __launch_bounds__(256) main_kernel(const float* __restrict__ db) {
    extern __shared__ char smem[];
    float* dsc_s = reinterpret_cast<float*>(smem);
    float* qsc_s = reinterpret_cast<float*>(smem + QSC_OFF);
    const int tid = threadIdx.x;
    const int lane = tid & 31, warp = tid >> 5;
    const uint32_t sb = smem_u32(smem);
    const uint32_t qsm = sb + QBASE, dsm = sb + DBBASE;

    // copy prebuilt query image (64 KB) + qscales into SMEM
    {
        const uint4* src = reinterpret_cast<const uint4*>(g_qn);
        uint4* dst = reinterpret_cast<uint4*>(smem + QBASE);
#pragma unroll
        for (int i = 0; i < 16; i++) dst[tid + i * 256] = src[tid + i * 256];
        if (tid < NQ) qsc_s[tid] = g_qscale[tid];
    }

    // db tile load mapping: thread -> (row = tid/8, 32 cols starting at (tid&7)*32)
    const int lrow = tid >> 3, le8 = tid & 7;
    float4 v[8];
    int tile = blockIdx.x;
    {
        const float4* g = reinterpret_cast<const float4*>(
            db + (size_t)(tile * TILE + lrow) * DDIM) + le8 * 8;
#pragma unroll
        for (int i = 0; i < 8; i++) v[i] = g[i];
    }
    __syncthreads();

    // MMA lane-invariant addressing (identical fragment bytes to verified bf16 path)
    const int mbase = warp * 32;
    const int rA0 = mbase + (lane & 15);
    const int rA1 = rA0 + 16;
    const int rB0 = (lane & 7) + ((lane >> 4) & 1) * 8;
    const int rB1 = rB0 + 16;
    const int gq = lane >> 2, tc = lane & 3;

    // per-thread query scales (rows fixed across the whole loop)
    float qs4[4];
#pragma unroll
    for (int mb = 0; mb < 2; mb++)
#pragma unroll
        for (int hf = 0; hf < 2; hf++)
            qs4[mb * 2 + hf] = qsc_s[mbase + mb * 16 + hf * 8 + gq];

    float best[4] = {-2.f, -2.f, -2.f, -2.f};

    for (; tile < NTILES; tile += GRID) {
        // ---- quantize staged fp32 -> int8 swizzled smem; per-row scale ----
        float ssq = 0.f, mx = 0.f;
#pragma unroll
        for (int i = 0; i < 8; i++) {
            ssq += v[i].x * v[i].x + v[i].y * v[i].y + v[i].z * v[i].z + v[i].w * v[i].w;
            mx = fmaxf(mx, fmaxf(fmaxf(fabsf(v[i].x), fabsf(v[i].y)),
                                 fmaxf(fabsf(v[i].z), fabsf(v[i].w))));
        }
#pragma unroll
        for (int o = 1; o < 8; o <<= 1) {
            ssq += __shfl_xor_sync(0xFFFFFFFFu, ssq, o);
            mx = fmaxf(mx, __shfl_xor_sync(0xFFFFFFFFu, mx, o));
        }
        float s = QMAX / fmaxf(mx, 1e-30f);
        if (le8 == 0)
            dsc_s[lrow] = (mx / QMAX) / fmaxf(sqrtf(ssq), EPSN);
        {
            uint4 pk;
            pk.x = pack_s8x4(v[0].x * s, v[0].y * s, v[0].z * s, v[0].w * s);
            pk.y = pack_s8x4(v[1].x * s, v[1].y * s, v[1].z * s, v[1].w * s);
            pk.z = pack_s8x4(v[2].x * s, v[2].y * s, v[2].z * s, v[2].w * s);
            pk.w = pack_s8x4(v[3].x * s, v[3].y * s, v[3].z * s, v[3].w * s);
            *reinterpret_cast<uint4*>(smem + DBBASE + SWZ8(lrow, le8 * 2)) = pk;
            pk.x = pack_s8x4(v[4].x * s, v[4].y * s, v[4].z * s, v[4].w * s);
            pk.y = pack_s8x4(v[5].x * s, v[5].y * s, v[5].z * s, v[5].w * s);
            pk.z = pack_s8x4(v[6].x * s, v[6].y * s, v[6].z * s, v[6].w * s);
            pk.w = pack_s8x4(v[7].x * s, v[7].y * s, v[7].z * s, v[7].w * s);
            *reinterpret_cast<uint4*>(smem + DBBASE + SWZ8(lrow, le8 * 2 + 1)) = pk;
        }
        __syncthreads();

        // ---- prefetch next tile into registers (drains during MMA) ----
        int nt = tile + GRID;
        if (nt < NTILES) {
            const float4* g = reinterpret_cast<const float4*>(
                db + (size_t)(nt * TILE + lrow) * DDIM) + le8 * 8;
#pragma unroll
            for (int i = 0; i < 8; i++) v[i] = g[i];
        }

        // ---- IMMA: warp computes [mbase..mbase+32) x [0..32) over K=256 int8 ----
        int acc[2][4][4];
#pragma unroll
        for (int mb = 0; mb < 2; mb++)
#pragma unroll
            for (int nb = 0; nb < 4; nb++)
#pragma unroll
                for (int c = 0; c < 4; c++) acc[mb][nb][c] = 0;

#pragma unroll
        for (int ks = 0; ks < 8; ks++) {   // 8 x k32 = K 256
            const int ua = ks * 2 + (lane >> 4);
            uint32_t a[2][4];
            LDSM4(a[0], qsm + SWZ8(rA0, ua));
            LDSM4(a[1], qsm + SWZ8(rA1, ua));
            const int ub = ks * 2 + ((lane >> 3) & 1);
            uint32_t b[4][2];
            {
                uint32_t r[4];
                LDSM4(r, dsm + SWZ8(rB0, ub));
                b[0][0] = r[0]; b[0][1] = r[1]; b[1][0] = r[2]; b[1][1] = r[3];
                LDSM4(r, dsm + SWZ8(rB1, ub));
                b[2][0] = r[0]; b[2][1] = r[1]; b[3][0] = r[2]; b[3][1] = r[3];
            }
#pragma unroll
            for (int mb = 0; mb < 2; mb++)
#pragma unroll
                for (int nb = 0; nb < 4; nb++)
                    imma16832(acc[mb][nb], a[mb], b[nb]);
        }

        // ---- epilogue: scale to cosine sim, margin-filtered running argmax ----
        float2 ds2[4];
#pragma unroll
        for (int nb = 0; nb < 4; nb++)
            ds2[nb] = *reinterpret_cast<const float2*>(&dsc_s[nb * 8 + tc * 2]);
#pragma unroll
        for (int mb = 0; mb < 2; mb++)
#pragma unroll
            for (int hf = 0; hf < 2; hf++) {
                const int ridx = mb * 2 + hf;
                const unsigned qrow = (unsigned)(mbase + mb * 16 + hf * 8 + gq);
                const float qs = qs4[ridx];
#pragma unroll
                for (int nb = 0; nb < 4; nb++)
#pragma unroll
                    for (int j = 0; j < 2; j++) {
                        float val = (float)acc[mb][nb][hf * 2 + j]
                                  * (qs * (j ? ds2[nb].y : ds2[nb].x));
                        if (val >= best[ridx] - MARGIN) {
                            unsigned idx = (unsigned)(tile * TILE + nb * 8 + tc * 2 + j);
                            unsigned pos = atomicAdd(&g_cnt, 1u);
                            if (pos < CAP)
                                g_rec[pos] = ((unsigned long long)f_sort(val) << 32)
                                           | ((unsigned long long)qrow << 20) | idx;
                            if (val > best[ridx]) best[ridx] = val;
                        }
                    }
            }
        __syncthreads();
    }

    // publish per-thread int8-sim bests (threshold source for rescue filter)
#pragma unroll
    for (int k = 0; k < 4; k++) {
        unsigned qrow = (unsigned)(mbase + (k >> 1) * 16 + (k & 1) * 8 + gq);
        atomicMax(&g_best[qrow], f_sort(best[k]));
    }
}

// ============ kernel 3: filter records, recompute exact fp32 sims for survivors ============
__global__ void rescue_kernel(const float* __restrict__ q, const float* __restrict__ db) {
    unsigned n = g_cnt;
    if (n > CAP) n = CAP;
    for (unsigned i = blockIdx.x * blockDim.x + threadIdx.x; i < n;
         i += gridDim.x * blockDim.x) {
        unsigned long long rec = g_rec[i];
        float simq = f_unsort((uint32_t)(rec >> 32));
        unsigned qi = (unsigned)(rec >> 20) & 0xFFu;
        unsigned idx = (unsigned)(rec & 0xFFFFFu);
        if (simq < f_unsort(g_best[qi]) - MARGIN) continue;
        const float4* qr = reinterpret_cast<const float4*>(q) + qi * (DDIM / 4);
        const float4* dr = reinterpret_cast<const float4*>(db) + (size_t)idx * (DDIM / 4);
        float dot = 0.f, dsq = 0.f;
#pragma unroll 8
        for (int k = 0; k < DDIM / 4; k++) {
            float4 a = qr[k], b = dr[k];
            dot += a.x * b.x + a.y * b.y + a.z * b.z + a.w * b.w;
            dsq += b.x * b.x + b.y * b.y + b.z * b.z + b.w * b.w;
        }
        float sim = dot / (fmaxf(g_qnorm[qi], EPSN) * fmaxf(sqrtf(dsq), EPSN));
        unsigned long long key = ((unsigned long long)f_sort(sim) << 32)
                               | (unsigned long long)(~idx);
        atomicMax(&g_final[qi], key);
    }
}

// ============ kernel 4: unpack, gather labels, write output ============
__global__ void finalize_kernel(const void* __restrict__ labels, float* __restrict__ out,
                                int out_size) {
    __shared__ int is32;
    if (threadIdx.x == 0) {
        const int* li = (const int*)labels;
        int nz = 0;
#pragma unroll
        for (int i = 0; i < 16; i++) nz |= li[2 * i + 1];
        is32 = nz;  // nonzero odd words -> int32 layout
    }
    __syncthreads();
    int qi = threadIdx.x;
    if (qi < NQ) {
        unsigned long long key = g_final[qi];
        float sim = f_unsort((uint32_t)(key >> 32));
        unsigned idx = ~((unsigned)(key & 0xFFFFFFFFull));
        long long lab;
        if (is32) lab = (long long)((const int*)labels)[idx];
        else      lab = ((const long long*)labels)[idx];
        out[qi] = sim;
        if (out_size >= 2 * NQ) out[NQ + qi] = (float)lab;
    }
}

// ============ entry point ============
extern "C" void kernel_launch(void* const* d_in, const int* in_sizes, int n_in,
                              void* d_out, int out_size) {
    (void)in_sizes; (void)n_in;
    const float* q  = (const float*)d_in[0];
    const float* db = (const float*)d_in[1];
    const void*  lb = d_in[2];
    float* out = (float*)d_out;

    cudaFuncSetAttribute(main_kernel, cudaFuncAttributeMaxDynamicSharedMemorySize, SMEM_TOTAL);

    prep_kernel<<<NQ * 32 / 256, 256>>>(q);
    main_kernel<<<GRID, 256, SMEM_TOTAL>>>(db);
    rescue_kernel<<<GRID, 256>>>(q, db);
    finalize_kernel<<<1, 256>>>(lb, out, out_size);
}

// round 9
// speedup vs baseline: 2.1681x; 2.1573x over previous
#include <cuda_runtime.h>
#include <cuda_bf16.h>
#include <cstdint>

// ---------------- problem constants ----------------
#define NQ      256
#define DDIM    256
#define NDB     500000
#define TILE    32
#define NTILES  (NDB / TILE)          // 15625, exact
#define GRID    152
#define MARGIN  4e-3f
#define EPSN    1e-8f
#define CAP     (8u * 1024u * 1024u)  // record buffer entries

// ---------------- smem layout ----------------------
// [0, 256)        dscale, 2 buffers x 32 floats
// [2048, 133120)  Q bf16 image: 256 rows x 512B, swizzled
// [133120, +2x16K) DB tile bf16, double buffered
#define QBASE      2048
#define QBYTES     (NQ * 512)
#define DBBASE     (QBASE + QBYTES)
#define DBSTRIDE   (TILE * 512)
#define SMEM_TOTAL (DBBASE + 2 * DBSTRIDE) // 165888

// swizzled byte offset within a 512B row image: u = 16B-unit index (0..31)
#define SWZ(row, u) (((uint32_t)(row)) * 512u + ((uint32_t)((u) ^ ((row) & 7)) << 4))

__device__ __align__(16) unsigned char g_qn[QBYTES];  // prebuilt swizzled bf16 queries
__device__ float              g_qnorm[NQ];
__device__ unsigned int       g_best[NQ];             // sortable-u32 bf16 best sim
__device__ unsigned long long g_final[NQ];            // (sortable exact sim | ~idx)
__device__ unsigned int       g_cnt;
__device__ unsigned long long g_rec[CAP];

// ---------------- helpers ----------------------
__device__ __forceinline__ uint32_t smem_u32(const void* p) {
    uint32_t a;
    asm("{ .reg .u64 t; cvta.to.shared.u64 t, %1; cvt.u32.u64 %0, t; }" : "=r"(a) : "l"(p));
    return a;
}
__device__ __forceinline__ uint32_t f_sort(float x) {
    uint32_t s = __float_as_uint(x);
    return (s & 0x80000000u) ? ~s : (s | 0x80000000u);
}
__device__ __forceinline__ float f_unsort(uint32_t s) {
    return __uint_as_float((s & 0x80000000u) ? (s & 0x7FFFFFFFu) : ~s);
}
__device__ __forceinline__ uint32_t pack_bf2(float x, float y) {
    __nv_bfloat162 h = __floats2bfloat162_rn(x, y);
    return *reinterpret_cast<uint32_t*>(&h);
}
#define LDSM4(r, addr)                                                        \
    asm volatile("ldmatrix.sync.aligned.m8n8.x4.shared.b16 {%0,%1,%2,%3}, [%4];" \
        : "=r"((r)[0]), "=r"((r)[1]), "=r"((r)[2]), "=r"((r)[3]) : "r"(addr))

__device__ __forceinline__ void mma16816(float* c, const uint32_t* a, const uint32_t* b) {
    asm volatile("mma.sync.aligned.m16n8k16.row.col.f32.bf16.bf16.f32 "
        "{%0,%1,%2,%3}, {%4,%5,%6,%7}, {%8,%9}, {%0,%1,%2,%3};"
        : "+f"(c[0]), "+f"(c[1]), "+f"(c[2]), "+f"(c[3])
        : "r"(a[0]), "r"(a[1]), "r"(a[2]), "r"(a[3]), "r"(b[0]), "r"(b[1]));
}

// ============ kernel 1: normalize queries -> swizzled bf16 image; init globals ============
__global__ void prep_kernel(const float* __restrict__ q) {
    int gtid = blockIdx.x * blockDim.x + threadIdx.x;
    if (gtid < NQ) { g_best[gtid] = 0u; g_final[gtid] = 0ull; }
    if (gtid == 0) g_cnt = 0u;
    int qi = gtid >> 5, lane = gtid & 31;
    if (qi >= NQ) return;
    const float4* row = reinterpret_cast<const float4*>(q + (size_t)qi * DDIM);
    float4 a = row[lane * 2], b = row[lane * 2 + 1];
    float ssq = a.x * a.x + a.y * a.y + a.z * a.z + a.w * a.w
              + b.x * b.x + b.y * b.y + b.z * b.z + b.w * b.w;
#pragma unroll
    for (int o = 16; o; o >>= 1) ssq += __shfl_xor_sync(0xFFFFFFFFu, ssq, o);
    float nrm = sqrtf(ssq);
    if (lane == 0) g_qnorm[qi] = nrm;
    float rn = 1.f / fmaxf(nrm, EPSN);
    uint4 pk;
    pk.x = pack_bf2(a.x * rn, a.y * rn);
    pk.y = pack_bf2(a.z * rn, a.w * rn);
    pk.z = pack_bf2(b.x * rn, b.y * rn);
    pk.w = pack_bf2(b.z * rn, b.w * rn);
    *reinterpret_cast<uint4*>(g_qn + SWZ(qi, lane)) = pk;
}

// ============ kernel 2: persistent bf16 HMMA GEMM + fed-back margin argmax ============
__global__ void __launch_bounds__(256) main_kernel(const float* __restrict__ db) {
    extern __shared__ char smem[];
    float* dsc_s = reinterpret_cast<float*>(smem);       // 2 x 32 floats
    const int tid = threadIdx.x;
    const int lane = tid & 31, warp = tid >> 5;
    const uint32_t sb = smem_u32(smem);
    const uint32_t qsm = sb + QBASE;
    const uint32_t lmlt = (1u << lane) - 1u;

    // copy prebuilt query image (128 KB) into SMEM
    {
        const uint4* src = reinterpret_cast<const uint4*>(g_qn);
        uint4* dst = reinterpret_cast<uint4*>(smem + QBASE);
#pragma unroll
        for (int i = 0; i < 32; i++) dst[tid + i * 256] = src[tid + i * 256];
    }

    // db tile load mapping: thread -> (row = tid/8, 32 cols starting at (tid&7)*32)
    const int lrow = tid >> 3, le8 = tid & 7;
    float4 v[8];
    int tile = blockIdx.x;
    {
        const float4* g = reinterpret_cast<const float4*>(
            db + (size_t)(tile * TILE + lrow) * DDIM) + le8 * 8;
#pragma unroll
        for (int i = 0; i < 8; i++) v[i] = g[i];
    }
    __syncthreads();

    // MMA lane-invariant addressing (verified in R6)
    const int mbase = warp * 32;
    const int rA0 = mbase + (lane & 15);
    const int rA1 = rA0 + 16;
    const int rB0 = (lane & 7) + ((lane >> 4) & 1) * 8;
    const int rB1 = rB0 + 16;
    const int gq = lane >> 2, tc = lane & 3;

    unsigned qrow4[4];
    float best[4];
#pragma unroll
    for (int k = 0; k < 4; k++) {
        qrow4[k] = (unsigned)(mbase + (k >> 1) * 16 + (k & 1) * 8 + gq);
        best[k] = -2.f;
    }

    int it = 0;
    for (; tile < NTILES; tile += GRID, ++it) {
        const uint32_t dbb = (uint32_t)(DBBASE + (it & 1) * DBSTRIDE);
        const uint32_t dsm = sb + dbb;
        float* dsc = dsc_s + (it & 1) * 32;

        // ---- convert staged fp32 -> bf16 swizzled smem, compute row rnorms ----
        float ssq = 0.f;
#pragma unroll
        for (int i = 0; i < 8; i++)
            ssq += v[i].x * v[i].x + v[i].y * v[i].y + v[i].z * v[i].z + v[i].w * v[i].w;
        ssq += __shfl_xor_sync(0xFFFFFFFFu, ssq, 1);
        ssq += __shfl_xor_sync(0xFFFFFFFFu, ssq, 2);
        ssq += __shfl_xor_sync(0xFFFFFFFFu, ssq, 4);
        if (le8 == 0) dsc[lrow] = 1.f / fmaxf(sqrtf(ssq), EPSN);
#pragma unroll
        for (int j = 0; j < 4; j++) {
            uint4 pk;
            pk.x = pack_bf2(v[2 * j].x, v[2 * j].y);
            pk.y = pack_bf2(v[2 * j].z, v[2 * j].w);
            pk.z = pack_bf2(v[2 * j + 1].x, v[2 * j + 1].y);
            pk.w = pack_bf2(v[2 * j + 1].z, v[2 * j + 1].w);
            *reinterpret_cast<uint4*>(smem + dbb + SWZ(lrow, le8 * 4 + j)) = pk;
        }
        __syncthreads();   // single barrier per tile (double-buffered)

        // ---- prefetch next tile into registers (drains during MMA) ----
        int nt = tile + GRID;
        if (nt < NTILES) {
            const float4* g = reinterpret_cast<const float4*>(
                db + (size_t)(nt * TILE + lrow) * DDIM) + le8 * 8;
#pragma unroll
            for (int i = 0; i < 8; i++) v[i] = g[i];
        }

        // ---- refresh local thresholds from global best (cross-CTA feedback) ----
        if ((it & 7) == 0) {
#pragma unroll
            for (int k = 0; k < 4; k++)
                best[k] = fmaxf(best[k], f_unsort(__ldcg(&g_best[qrow4[k]])));
        }

        // ---- MMA: warp computes [mbase..mbase+32) x [0..32) over K=256 ----
        float acc[2][4][4];
#pragma unroll
        for (int mb = 0; mb < 2; mb++)
#pragma unroll
            for (int nb = 0; nb < 4; nb++)
#pragma unroll
                for (int c = 0; c < 4; c++) acc[mb][nb][c] = 0.f;

#pragma unroll
        for (int ks = 0; ks < 16; ks++) {
            const int ua = ks * 2 + (lane >> 4);
            uint32_t a[2][4];
            LDSM4(a[0], qsm + SWZ(rA0, ua));
            LDSM4(a[1], qsm + SWZ(rA1, ua));
            const int ub = ks * 2 + ((lane >> 3) & 1);
            uint32_t b[4][2];
            {
                uint32_t r[4];
                LDSM4(r, dsm + SWZ(rB0, ub));
                b[0][0] = r[0]; b[0][1] = r[1]; b[1][0] = r[2]; b[1][1] = r[3];
                LDSM4(r, dsm + SWZ(rB1, ub));
                b[2][0] = r[0]; b[2][1] = r[1]; b[3][0] = r[2]; b[3][1] = r[3];
            }
#pragma unroll
            for (int mb = 0; mb < 2; mb++)
#pragma unroll
                for (int nb = 0; nb < 4; nb++)
                    mma16816(acc[mb][nb], a[mb], b[nb]);
        }

        // ---- epilogue: tmax-first, ballot-aggregated rare record push ----
        float2 ds2[4];
#pragma unroll
        for (int nb = 0; nb < 4; nb++)
            ds2[nb] = *reinterpret_cast<const float2*>(&dsc[nb * 8 + tc * 2]);

#pragma unroll
        for (int mb = 0; mb < 2; mb++)
#pragma unroll
            for (int hf = 0; hf < 2; hf++) {
                const int ridx = mb * 2 + hf;
                float vals[8], tmax = -2.f;
#pragma unroll
                for (int nb = 0; nb < 4; nb++)
#pragma unroll
                    for (int j = 0; j < 2; j++) {
                        float val = acc[mb][nb][hf * 2 + j] * (j ? ds2[nb].y : ds2[nb].x);
                        vals[nb * 2 + j] = val;
                        tmax = fmaxf(tmax, val);
                    }
                const bool want = tmax >= best[ridx] - MARGIN;
                if (__ballot_sync(0xFFFFFFFFu, want)) {
                    const float thr = fmaxf(best[ridx], tmax) - MARGIN;
                    const unsigned qrow = qrow4[ridx];
#pragma unroll
                    for (int c = 0; c < 8; c++) {
                        bool cnd = want && (vals[c] >= thr);
                        unsigned mask = __ballot_sync(0xFFFFFFFFu, cnd);
                        if (mask) {
                            int leader = __ffs(mask) - 1;
                            unsigned base = 0;
                            if (lane == leader) base = atomicAdd(&g_cnt, (unsigned)__popc(mask));
                            base = __shfl_sync(0xFFFFFFFFu, base, leader);
                            if (cnd) {
                                unsigned pos = base + (unsigned)__popc(mask & lmlt);
                                unsigned idx = (unsigned)(tile * TILE + (c >> 1) * 8 + tc * 2 + (c & 1));
                                if (pos < CAP)
                                    g_rec[pos] = ((unsigned long long)f_sort(vals[c]) << 32)
                                               | ((unsigned long long)qrow << 20) | idx;
                            }
                        }
                    }
                    if (want && tmax > best[ridx]) {
                        atomicMax(&g_best[qrow], f_sort(tmax));
                        best[ridx] = tmax;
                    }
                }
            }
        // no trailing barrier: next iteration writes the other buffer
    }

    // final publication (cheap; keeps g_best complete)
#pragma unroll
    for (int k = 0; k < 4; k++) atomicMax(&g_best[qrow4[k]], f_sort(best[k]));
}

// ============ kernel 3: filter records, recompute exact fp32 sims for survivors ============
__global__ void rescue_kernel(const float* __restrict__ q, const float* __restrict__ db) {
    unsigned n = g_cnt;
    if (n > CAP) n = CAP;
    for (unsigned i = blockIdx.x * blockDim.x + threadIdx.x; i < n;
         i += gridDim.x * blockDim.x) {
        unsigned long long rec = g_rec[i];
        float simbf = f_unsort((uint32_t)(rec >> 32));
        unsigned qi = (unsigned)(rec >> 20) & 0xFFu;
        unsigned idx = (unsigned)(rec & 0xFFFFFu);
        if (simbf < f_unsort(g_best[qi]) - MARGIN) continue;
        const float4* qr = reinterpret_cast<const float4*>(q) + qi * (DDIM / 4);
        const float4* dr = reinterpret_cast<const float4*>(db) + (size_t)idx * (DDIM / 4);
        float dot = 0.f, dsq = 0.f;
#pragma unroll 8
        for (int k = 0; k < DDIM / 4; k++) {
            float4 a = qr[k], b = dr[k];
            dot += a.x * b.x + a.y * b.y + a.z * b.z + a.w * b.w;
            dsq += b.x * b.x + b.y * b.y + b.z * b.z + b.w * b.w;
        }
        float sim = dot / (fmaxf(g_qnorm[qi], EPSN) * fmaxf(sqrtf(dsq), EPSN));
        unsigned long long key = ((unsigned long long)f_sort(sim) << 32)
                               | (unsigned long long)(~idx);
        atomicMax(&g_final[qi], key);
    }
}

// ============ kernel 4: unpack, gather labels, write output ============
__global__ void finalize_kernel(const void* __restrict__ labels, float* __restrict__ out,
                                int out_size) {
    __shared__ int is32;
    if (threadIdx.x == 0) {
        const int* li = (const int*)labels;
        int nz = 0;
#pragma unroll
        for (int i = 0; i < 16; i++) nz |= li[2 * i + 1];
        is32 = nz;  // nonzero odd words -> int32 layout
    }
    __syncthreads();
    int qi = threadIdx.x;
    if (qi < NQ) {
        unsigned long long key = g_final[qi];
        float sim = f_unsort((uint32_t)(key >> 32));
        unsigned idx = ~((unsigned)(key & 0xFFFFFFFFull));
        long long lab;
        if (is32) lab = (long long)((const int*)labels)[idx];
        else      lab = ((const long long*)labels)[idx];
        out[qi] = sim;
        if (out_size >= 2 * NQ) out[NQ + qi] = (float)lab;
    }
}

// ============ entry point ============
extern "C" void kernel_launch(void* const* d_in, const int* in_sizes, int n_in,
                              void* d_out, int out_size) {
    (void)in_sizes; (void)n_in;
    const float* q  = (const float*)d_in[0];
    const float* db = (const float*)d_in[1];
    const void*  lb = d_in[2];
    float* out = (float*)d_out;

    cudaFuncSetAttribute(main_kernel, cudaFuncAttributeMaxDynamicSharedMemorySize, SMEM_TOTAL);

    prep_kernel<<<NQ * 32 / 256, 256>>>(q);
    main_kernel<<<GRID, 256, SMEM_TOTAL>>>(db);
    rescue_kernel<<<GRID, 256>>>(q, db);
    finalize_kernel<<<1, 256>>>(lb, out, out_size);
}

// round 10
// speedup vs baseline: 2.1878x; 1.0091x over previous
#include <cuda_runtime.h>
#include <cuda_bf16.h>
#include <cstdint>

// ---------------- problem constants ----------------
#define NQ      256
#define DDIM    256
#define NDB     500000
#define TILE    32
#define NTILES  (NDB / TILE)          // 15625, exact
#define GRID    152
#define MARGIN  4e-3f
#define EPSN    1e-8f
#define CAP     (8u * 1024u * 1024u)  // record buffer entries

// ---------------- smem layout ----------------------
// [0, 256)        dscale, 2 buffers x 32 floats
// [2048, 133120)  Q bf16 image: 256 rows x 512B, swizzled
// [133120, +2x16K) DB tile bf16, double buffered
#define QBASE      2048
#define QBYTES     (NQ * 512)
#define DBBASE     (QBASE + QBYTES)
#define DBSTRIDE   (TILE * 512)
#define SMEM_TOTAL (DBBASE + 2 * DBSTRIDE) // 165888

// swizzled byte offset within a 512B row image: u = 16B-unit index (0..31)
#define SWZ(row, u) (((uint32_t)(row)) * 512u + ((uint32_t)((u) ^ ((row) & 7)) << 4))

__device__ __align__(16) unsigned char g_qn[QBYTES];  // prebuilt swizzled bf16 queries
__device__ float              g_qnorm[NQ];
__device__ unsigned int       g_best[NQ];             // sortable-u32 bf16 best sim
__device__ unsigned long long g_final[NQ];            // (sortable exact sim | ~idx)
__device__ unsigned int       g_cnt;
__device__ unsigned long long g_rec[CAP];

// ---------------- helpers ----------------------
__device__ __forceinline__ uint32_t smem_u32(const void* p) {
    uint32_t a;
    asm("{ .reg .u64 t; cvta.to.shared.u64 t, %1; cvt.u32.u64 %0, t; }" : "=r"(a) : "l"(p));
    return a;
}
__device__ __forceinline__ uint32_t f_sort(float x) {
    uint32_t s = __float_as_uint(x);
    return (s & 0x80000000u) ? ~s : (s | 0x80000000u);
}
__device__ __forceinline__ float f_unsort(uint32_t s) {
    return __uint_as_float((s & 0x80000000u) ? (s & 0x7FFFFFFFu) : ~s);
}
__device__ __forceinline__ uint32_t pack_bf2(float x, float y) {
    __nv_bfloat162 h = __floats2bfloat162_rn(x, y);
    return *reinterpret_cast<uint32_t*>(&h);
}
#define LDSM4(r, addr)                                                        \
    asm volatile("ldmatrix.sync.aligned.m8n8.x4.shared.b16 {%0,%1,%2,%3}, [%4];" \
        : "=r"((r)[0]), "=r"((r)[1]), "=r"((r)[2]), "=r"((r)[3]) : "r"(addr))

__device__ __forceinline__ void mma16816(float* c, const uint32_t* a, const uint32_t* b) {
    asm volatile("mma.sync.aligned.m16n8k16.row.col.f32.bf16.bf16.f32 "
        "{%0,%1,%2,%3}, {%4,%5,%6,%7}, {%8,%9}, {%0,%1,%2,%3};"
        : "+f"(c[0]), "+f"(c[1]), "+f"(c[2]), "+f"(c[3])
        : "r"(a[0]), "r"(a[1]), "r"(a[2]), "r"(a[3]), "r"(b[0]), "r"(b[1]));
}

// ============ kernel 1: normalize queries -> swizzled bf16 image; init globals ============
__global__ void prep_kernel(const float* __restrict__ q) {
    int gtid = blockIdx.x * blockDim.x + threadIdx.x;
    if (gtid < NQ) { g_best[gtid] = 0u; g_final[gtid] = 0ull; }
    if (gtid == 0) g_cnt = 0u;
    int qi = gtid >> 5, lane = gtid & 31;
    if (qi >= NQ) return;
    const float4* row = reinterpret_cast<const float4*>(q + (size_t)qi * DDIM);
    float4 a = row[lane * 2], b = row[lane * 2 + 1];
    float ssq = a.x * a.x + a.y * a.y + a.z * a.z + a.w * a.w
              + b.x * b.x + b.y * b.y + b.z * b.z + b.w * b.w;
#pragma unroll
    for (int o = 16; o; o >>= 1) ssq += __shfl_xor_sync(0xFFFFFFFFu, ssq, o);
    float nrm = sqrtf(ssq);
    if (lane == 0) g_qnorm[qi] = nrm;
    float rn = 1.f / fmaxf(nrm, EPSN);
    uint4 pk;
    pk.x = pack_bf2(a.x * rn, a.y * rn);
    pk.y = pack_bf2(a.z * rn, a.w * rn);
    pk.z = pack_bf2(b.x * rn, b.y * rn);
    pk.w = pack_bf2(b.z * rn, b.w * rn);
    *reinterpret_cast<uint4*>(g_qn + SWZ(qi, lane)) = pk;
}

// ============ kernel 2: persistent bf16 HMMA GEMM + fed-back margin argmax ============
__global__ void __launch_bounds__(256) main_kernel(const float* __restrict__ db) {
    extern __shared__ char smem[];
    float* dsc_s = reinterpret_cast<float*>(smem);       // 2 x 32 floats
    const int tid = threadIdx.x;
    const int lane = tid & 31, warp = tid >> 5;
    const uint32_t sb = smem_u32(smem);
    const uint32_t qsm = sb + QBASE;
    const uint32_t lmlt = (1u << lane) - 1u;

    // copy prebuilt query image (128 KB) into SMEM
    {
        const uint4* src = reinterpret_cast<const uint4*>(g_qn);
        uint4* dst = reinterpret_cast<uint4*>(smem + QBASE);
#pragma unroll
        for (int i = 0; i < 32; i++) dst[tid + i * 256] = src[tid + i * 256];
    }

    // db tile load mapping: thread -> (row = tid/8, 32 cols starting at (tid&7)*32)
    const int lrow = tid >> 3, le8 = tid & 7;
    float4 v[8];
    int tile = blockIdx.x;
    {
        const float4* g = reinterpret_cast<const float4*>(
            db + (size_t)(tile * TILE + lrow) * DDIM) + le8 * 8;
#pragma unroll
        for (int i = 0; i < 8; i++) v[i] = g[i];
    }
    __syncthreads();

    // MMA lane-invariant addressing (verified in R6)
    const int mbase = warp * 32;
    const int rA0 = mbase + (lane & 15);
    const int rA1 = rA0 + 16;
    const int rB0 = (lane & 7) + ((lane >> 4) & 1) * 8;
    const int rB1 = rB0 + 16;
    const int gq = lane >> 2, tc = lane & 3;

    unsigned qrow4[4];
    float best[4];
#pragma unroll
    for (int k = 0; k < 4; k++) {
        qrow4[k] = (unsigned)(mbase + (k >> 1) * 16 + (k & 1) * 8 + gq);
        best[k] = -2.f;
    }

    int it = 0;
    for (; tile < NTILES; tile += GRID, ++it) {
        const uint32_t dbb = (uint32_t)(DBBASE + (it & 1) * DBSTRIDE);
        const uint32_t dsm = sb + dbb;
        float* dsc = dsc_s + (it & 1) * 32;

        // ---- convert staged fp32 -> bf16 swizzled smem, compute row rnorms ----
        float ssq = 0.f;
#pragma unroll
        for (int i = 0; i < 8; i++)
            ssq += v[i].x * v[i].x + v[i].y * v[i].y + v[i].z * v[i].z + v[i].w * v[i].w;
        ssq += __shfl_xor_sync(0xFFFFFFFFu, ssq, 1);
        ssq += __shfl_xor_sync(0xFFFFFFFFu, ssq, 2);
        ssq += __shfl_xor_sync(0xFFFFFFFFu, ssq, 4);
        if (le8 == 0) dsc[lrow] = 1.f / fmaxf(sqrtf(ssq), EPSN);
#pragma unroll
        for (int j = 0; j < 4; j++) {
            uint4 pk;
            pk.x = pack_bf2(v[2 * j].x, v[2 * j].y);
            pk.y = pack_bf2(v[2 * j].z, v[2 * j].w);
            pk.z = pack_bf2(v[2 * j + 1].x, v[2 * j + 1].y);
            pk.w = pack_bf2(v[2 * j + 1].z, v[2 * j + 1].w);
            *reinterpret_cast<uint4*>(smem + dbb + SWZ(lrow, le8 * 4 + j)) = pk;
        }
        __syncthreads();   // single barrier per tile (double-buffered)

        // ---- prefetch next tile into registers (drains during MMA) ----
        int nt = tile + GRID;
        if (nt < NTILES) {
            const float4* g = reinterpret_cast<const float4*>(
                db + (size_t)(nt * TILE + lrow) * DDIM) + le8 * 8;
#pragma unroll
            for (int i = 0; i < 8; i++) v[i] = g[i];
        }

        // ---- refresh local thresholds from global best (cross-CTA feedback) ----
        if ((it & 7) == 0) {
#pragma unroll
            for (int k = 0; k < 4; k++)
                best[k] = fmaxf(best[k], f_unsort(__ldcg(&g_best[qrow4[k]])));
        }

        // ---- MMA: warp computes [mbase..mbase+32) x [0..32) over K=256 ----
        float acc[2][4][4];
#pragma unroll
        for (int mb = 0; mb < 2; mb++)
#pragma unroll
            for (int nb = 0; nb < 4; nb++)
#pragma unroll
                for (int c = 0; c < 4; c++) acc[mb][nb][c] = 0.f;

#pragma unroll
        for (int ks = 0; ks < 16; ks++) {
            const int ua = ks * 2 + (lane >> 4);
            uint32_t a[2][4];
            LDSM4(a[0], qsm + SWZ(rA0, ua));
            LDSM4(a[1], qsm + SWZ(rA1, ua));
            const int ub = ks * 2 + ((lane >> 3) & 1);
            uint32_t b[4][2];
            {
                uint32_t r[4];
                LDSM4(r, dsm + SWZ(rB0, ub));
                b[0][0] = r[0]; b[0][1] = r[1]; b[1][0] = r[2]; b[1][1] = r[3];
                LDSM4(r, dsm + SWZ(rB1, ub));
                b[2][0] = r[0]; b[2][1] = r[1]; b[3][0] = r[2]; b[3][1] = r[3];
            }
#pragma unroll
            for (int mb = 0; mb < 2; mb++)
#pragma unroll
                for (int nb = 0; nb < 4; nb++)
                    mma16816(acc[mb][nb], a[mb], b[nb]);
        }

        // ---- epilogue: tmax-first, ballot-aggregated rare record push ----
        float2 ds2[4];
#pragma unroll
        for (int nb = 0; nb < 4; nb++)
            ds2[nb] = *reinterpret_cast<const float2*>(&dsc[nb * 8 + tc * 2]);

#pragma unroll
        for (int mb = 0; mb < 2; mb++)
#pragma unroll
            for (int hf = 0; hf < 2; hf++) {
                const int ridx = mb * 2 + hf;
                float vals[8], tmax = -2.f;
#pragma unroll
                for (int nb = 0; nb < 4; nb++)
#pragma unroll
                    for (int j = 0; j < 2; j++) {
                        float val = acc[mb][nb][hf * 2 + j] * (j ? ds2[nb].y : ds2[nb].x);
                        vals[nb * 2 + j] = val;
                        tmax = fmaxf(tmax, val);
                    }
                const bool want = tmax >= best[ridx] - MARGIN;
                if (__ballot_sync(0xFFFFFFFFu, want)) {
                    const float thr = fmaxf(best[ridx], tmax) - MARGIN;
                    const unsigned qrow = qrow4[ridx];
#pragma unroll
                    for (int c = 0; c < 8; c++) {
                        bool cnd = want && (vals[c] >= thr);
                        unsigned mask = __ballot_sync(0xFFFFFFFFu, cnd);
                        if (mask) {
                            int leader = __ffs(mask) - 1;
                            unsigned base = 0;
                            if (lane == leader) base = atomicAdd(&g_cnt, (unsigned)__popc(mask));
                            base = __shfl_sync(0xFFFFFFFFu, base, leader);
                            if (cnd) {
                                unsigned pos = base + (unsigned)__popc(mask & lmlt);
                                unsigned idx = (unsigned)(tile * TILE + (c >> 1) * 8 + tc * 2 + (c & 1));
                                if (pos < CAP)
                                    g_rec[pos] = ((unsigned long long)f_sort(vals[c]) << 32)
                                               | ((unsigned long long)qrow << 20) | idx;
                            }
                        }
                    }
                    if (want && tmax > best[ridx]) {
                        atomicMax(&g_best[qrow], f_sort(tmax));
                        best[ridx] = tmax;
                    }
                }
            }
        // no trailing barrier: next iteration writes the other buffer
    }

    // final publication (cheap; keeps g_best complete)
#pragma unroll
    for (int k = 0; k < 4; k++) atomicMax(&g_best[qrow4[k]], f_sort(best[k]));
}

// ============ kernel 3: filter records, recompute exact fp32 sims for survivors ============
__global__ void rescue_kernel(const float* __restrict__ q, const float* __restrict__ db) {
    unsigned n = g_cnt;
    if (n > CAP) n = CAP;
    for (unsigned i = blockIdx.x * blockDim.x + threadIdx.x; i < n;
         i += gridDim.x * blockDim.x) {
        unsigned long long rec = g_rec[i];
        float simbf = f_unsort((uint32_t)(rec >> 32));
        unsigned qi = (unsigned)(rec >> 20) & 0xFFu;
        unsigned idx = (unsigned)(rec & 0xFFFFFu);
        if (simbf < f_unsort(g_best[qi]) - MARGIN) continue;
        const float4* qr = reinterpret_cast<const float4*>(q) + qi * (DDIM / 4);
        const float4* dr = reinterpret_cast<const float4*>(db) + (size_t)idx * (DDIM / 4);
        float dot = 0.f, dsq = 0.f;
#pragma unroll 8
        for (int k = 0; k < DDIM / 4; k++) {
            float4 a = qr[k], b = dr[k];
            dot += a.x * b.x + a.y * b.y + a.z * b.z + a.w * b.w;
            dsq += b.x * b.x + b.y * b.y + b.z * b.z + b.w * b.w;
        }
        float sim = dot / (fmaxf(g_qnorm[qi], EPSN) * fmaxf(sqrtf(dsq), EPSN));
        unsigned long long key = ((unsigned long long)f_sort(sim) << 32)
                               | (unsigned long long)(~idx);
        atomicMax(&g_final[qi], key);
    }
}

// ============ kernel 4: unpack, gather labels, write output ============
__global__ void finalize_kernel(const void* __restrict__ labels, float* __restrict__ out,
                                int out_size) {
    __shared__ int is32;
    if (threadIdx.x == 0) {
        const int* li = (const int*)labels;
        int nz = 0;
#pragma unroll
        for (int i = 0; i < 16; i++) nz |= li[2 * i + 1];
        is32 = nz;  // nonzero odd words -> int32 layout
    }
    __syncthreads();
    int qi = threadIdx.x;
    if (qi < NQ) {
        unsigned long long key = g_final[qi];
        float sim = f_unsort((uint32_t)(key >> 32));
        unsigned idx = ~((unsigned)(key & 0xFFFFFFFFull));
        long long lab;
        if (is32) lab = (long long)((const int*)labels)[idx];
        else      lab = ((const long long*)labels)[idx];
        out[qi] = sim;
        if (out_size >= 2 * NQ) out[NQ + qi] = (float)lab;
    }
}

// ============ entry point ============
extern "C" void kernel_launch(void* const* d_in, const int* in_sizes, int n_in,
                              void* d_out, int out_size) {
    (void)in_sizes; (void)n_in;
    const float* q  = (const float*)d_in[0];
    const float* db = (const float*)d_in[1];
    const void*  lb = d_in[2];
    float* out = (float*)d_out;

    cudaFuncSetAttribute(main_kernel, cudaFuncAttributeMaxDynamicSharedMemorySize, SMEM_TOTAL);

    prep_kernel<<<NQ * 32 / 256, 256>>>(q);
    main_kernel<<<GRID, 256, SMEM_TOTAL>>>(db);
    rescue_kernel<<<GRID, 256>>>(q, db);
    finalize_kernel<<<1, 256>>>(lb, out, out_size);
}